// round 2
// baseline (speedup 1.0000x reference)
#include <cuda_runtime.h>
#include <math_constants.h>

// Hausdorff distance between edge sets of two binary 128^3 masks, batch=2.
// Exact integer squared-EDT (Meijster) per edge set; directed max gathered at
// the partner set's edge voxels. Output: 2 floats.

#define DWH 128
#define NVOL 4                      // (b0,in) (b0,tgt) (b1,in) (b1,tgt)
#define VOXELS (128 * 128 * 128)
#define INF1D 16384                 // > any 1D distance (127)

// ---- scratch: __device__ globals (no allocation allowed) ----
__device__ unsigned int   g_mask[NVOL][DWH][DWH][4];   // bit-packed masks, 1MB
__device__ unsigned int   g_edge[NVOL][DWH][DWH][4];   // bit-packed edges, 1MB
__device__ unsigned short g_dt2[NVOL][VOXELS];         // phase-2 sq-dist (clamped), 16MB
__device__ int            g_cnt[NVOL];                 // edge voxel counts
__device__ int            g_dirmax[NVOL];              // max EDT_v over partner edges

// ============================================================================
// Kernel 1: binarize inputs (>0) into bit-packed masks via warp ballot.
// Also zeroes the accumulators (consumed only by later kernels).
// ============================================================================
__global__ void __launch_bounds__(256) k_binarize(
    const float* __restrict__ inputs, const float* __restrict__ targets)
{
    int gt = blockIdx.x * blockDim.x + threadIdx.x;   // 8,388,608 threads
    if (gt < 8) {
        if (gt < 4) g_cnt[gt] = 0;
        else        g_dirmax[gt - 4] = 0;
    }
    int lane = gt & 31;
    int c    = gt >> 5;              // chunk id, 262144 total (one warp each)
    int v    = c >> 16;              // 65536 chunks per volume
    int rem  = c & 65535;
    int z    = rem >> 9;
    int y    = (rem >> 2) & 127;
    int w    = rem & 3;
    int x    = (w << 5) + lane;

    const float* src = (v & 1) ? targets : inputs;
    int b = v >> 1;
    float val = src[(size_t)b * VOXELS + z * 16384 + y * 128 + x];
    unsigned int bal = __ballot_sync(0xFFFFFFFFu, val > 0.0f);
    if (lane == 0) g_mask[v][z][y][w] = bal;
}

// ============================================================================
// Kernel 2: edge = (~mask) & (3x3x3 box-OR of mask). Bitwise per (v,z,y) row.
// Box-OR = OR of 9 neighbor rows, then 1-bit dilation along x (word carries).
// Also accumulates edge-voxel counts (emptiness check).
// ============================================================================
__global__ void __launch_bounds__(128) k_edge()
{
    int t = blockIdx.x * blockDim.x + threadIdx.x;    // 65536 rows
    int v = t >> 14;
    int z = (t >> 7) & 127;
    int y = t & 127;

    unsigned int a0 = 0, a1 = 0, a2 = 0, a3 = 0;
    #pragma unroll
    for (int dz = -1; dz <= 1; dz++) {
        int zz = z + dz;
        if (zz < 0 || zz > 127) continue;
        #pragma unroll
        for (int dy = -1; dy <= 1; dy++) {
            int yy = y + dy;
            if (yy < 0 || yy > 127) continue;
            const unsigned int* r = g_mask[v][zz][yy];
            a0 |= r[0]; a1 |= r[1]; a2 |= r[2]; a3 |= r[3];
        }
    }
    // dilate along x across the 128-bit row (word carries)
    unsigned int d0 = a0 | (a0 << 1)               | (a0 >> 1) | (a1 << 31);
    unsigned int d1 = a1 | (a1 << 1) | (a0 >> 31)  | (a1 >> 1) | (a2 << 31);
    unsigned int d2 = a2 | (a2 << 1) | (a1 >> 31)  | (a2 >> 1) | (a3 << 31);
    unsigned int d3 = a3 | (a3 << 1) | (a2 >> 31)  | (a3 >> 1);

    const unsigned int* m = g_mask[v][z][y];
    unsigned int e0 = d0 & ~m[0], e1 = d1 & ~m[1], e2 = d2 & ~m[2], e3 = d3 & ~m[3];
    unsigned int* o = g_edge[v][z][y];
    o[0] = e0; o[1] = e1; o[2] = e2; o[3] = e3;

    int cnt = __popc(e0) + __popc(e1) + __popc(e2) + __popc(e3);
    #pragma unroll
    for (int off = 16; off; off >>= 1)
        cnt += __shfl_down_sync(0xFFFFFFFFu, cnt, off);
    // each warp covers a single v (v-boundaries are multiples of 16384 rows)
    if ((threadIdx.x & 31) == 0) atomicAdd(&g_cnt[v], cnt);
}

// ============================================================================
// Kernel 3: EDT phase 1 (nearest-site 1D distance along x, from edge bits)
//           + phase 2 (Meijster lower envelope along y), one z-slice per block.
// Output dt2 clamped to uint16: true final distances are <= 48387, so any
// clamped candidate (>=65535) can never win the phase-3 min when the site set
// is non-empty -> lossless clamp, halves dt2 traffic.
// ============================================================================
__global__ void __launch_bounds__(128) k_phase12()
{
    __shared__ short gsm[128 * 129];                 // 1D dists g(x,y), pitch 129
    int v = blockIdx.x >> 7;
    int z = blockIdx.x & 127;
    int tid = threadIdx.x;

    // ---- phase 1: thread = y-row, scan along x over edge bits ----
    {
        int y = tid;
        const unsigned int* e = g_edge[v][z][y];
        short* row = &gsm[y * 129];
        int g = INF1D;
        #pragma unroll
        for (int w = 0; w < 4; w++) {
            unsigned int word = e[w];
            short* r = row + w * 32;
            #pragma unroll
            for (int i = 0; i < 32; i++) {
                g = ((word >> i) & 1) ? 0 : g + 1;   // max 16384+127, fits short
                r[i] = (short)g;
            }
        }
        int prev = row[127];
        for (int x = 126; x >= 0; x--) {
            int c = row[x];
            int nv = prev + 1;
            if (c < nv) nv = c;
            row[x] = (short)nv;
            prev = nv;
        }
    }
    __syncthreads();

    // ---- phase 2: thread = x-column, Meijster along y. f(i) = g(i)^2 ----
    {
        int x = tid;
        int s[128], tt[128];                          // sites / segment starts
        auto f = [&](int i) { int gg = gsm[i * 129 + x]; return gg * gg; };
        int q = 0; s[0] = 0; tt[0] = 0;
        for (int u = 1; u < 128; u++) {
            int fu = f(u);
            while (q >= 0) {
                int tq = tt[q], sq = s[q];
                int a = tq - sq, b = tq - u;
                if (a * a + f(sq) > b * b + fu) q--;
                else break;
            }
            if (q < 0) { q = 0; s[0] = u; }
            else {
                int sq = s[q];
                int w = 1 + (u * u - sq * sq + fu - f(sq)) / (2 * (u - sq));
                if (w < 128) { q++; s[q] = u; tt[q] = w; }
            }
        }
        unsigned short* dt = &g_dt2[v][z * 16384 + x];
        for (int u = 127; u >= 0; u--) {
            int sq  = s[q];
            int val = (u - sq) * (u - sq) + f(sq);
            if (val > 65535) val = 65535;            // lossless clamp (see above)
            dt[u * 128] = (unsigned short)val;
            if (u == tt[q]) q--;
        }
    }
}

// ============================================================================
// Kernel 4: EDT phase 3 (Meijster along z) fused with the gather:
// final EDT values are only consulted at the PARTNER volume's edge voxels,
// reduced to a per-direction max. No dt3 writeback.
// Block = (v, y, x-half of 64), smem tile dt2[z][x] = 33KB.
// ============================================================================
__global__ void __launch_bounds__(64) k_phase3()
{
    __shared__ int tile[128 * 65];                   // pitch 65
    int v  = blockIdx.x >> 8;
    int y  = (blockIdx.x >> 1) & 127;
    int xh = blockIdx.x & 1;
    int tx = threadIdx.x;
    int x  = xh * 64 + tx;

    // load the [z][x] column tile (strided over z; each thread reads its x)
    const unsigned short* dt = &g_dt2[v][y * 128 + x];
    #pragma unroll 16
    for (int z = 0; z < 128; z++)
        tile[z * 65 + tx] = dt[z * 16384];
    __syncthreads();

    auto f = [&](int i) { return tile[i * 65 + tx]; };
    int s[128], tt[128];
    int q = 0; s[0] = 0; tt[0] = 0;
    for (int u = 1; u < 128; u++) {
        int fu = f(u);
        while (q >= 0) {
            int tq = tt[q], sq = s[q];
            int a = tq - sq, b = tq - u;
            if (a * a + f(sq) > b * b + fu) q--;
            else break;
        }
        if (q < 0) { q = 0; s[0] = u; }
        else {
            int sq = s[q];
            int w = 1 + (u * u - sq * sq + fu - f(sq)) / (2 * (u - sq));
            if (w < 128) { q++; s[q] = u; tt[q] = w; }
        }
    }

    int pv   = v ^ 1;                                // partner volume
    int wrd  = x >> 5, sh = x & 31;
    int lmax = -1;
    for (int u = 127; u >= 0; u--) {
        int sq  = s[q];
        int val = (u - sq) * (u - sq) + f(sq);
        unsigned int eb = g_edge[pv][u][y][wrd];
        if ((eb >> sh) & 1) { if (val > lmax) lmax = val; }
        if (u == tt[q]) q--;
    }

    // block max over 64 threads -> one atomic per block
    #pragma unroll
    for (int off = 16; off; off >>= 1) {
        int o = __shfl_down_sync(0xFFFFFFFFu, lmax, off);
        if (o > lmax) lmax = o;
    }
    __shared__ int wmax[2];
    if ((tx & 31) == 0) wmax[tx >> 5] = lmax;
    __syncthreads();
    if (tx == 0) {
        int m = wmax[0] > wmax[1] ? wmax[0] : wmax[1];
        if (m >= 0) atomicMax(&g_dirmax[v], m);
    }
}

// ============================================================================
// Kernel 5: finalize. hd[b] = sqrt(max of the two directed squared maxima),
// inf if either edge set is empty.
// ============================================================================
__global__ void k_final(float* __restrict__ out)
{
    int b = threadIdx.x;
    if (b < 2) {
        int vA = 2 * b, vB = 2 * b + 1;
        bool empty = (g_cnt[vA] == 0) || (g_cnt[vB] == 0);
        int m = g_dirmax[vA] > g_dirmax[vB] ? g_dirmax[vA] : g_dirmax[vB];
        out[b] = empty ? CUDART_INF_F : sqrtf((float)m);
    }
}

// ============================================================================
extern "C" void kernel_launch(void* const* d_in, const int* in_sizes, int n_in,
                              void* d_out, int out_size)
{
    const float* inputs  = (const float*)d_in[0];
    const float* targets = (const float*)d_in[1];
    float* out = (float*)d_out;

    k_binarize<<<32768, 256>>>(inputs, targets);
    k_edge    <<<512, 128>>>();
    k_phase12 <<<512, 128>>>();
    k_phase3  <<<1024, 64>>>();
    k_final   <<<1, 32>>>(out);
}